// round 7
// baseline (speedup 1.0000x reference)
#include <cuda_runtime.h>

#define EPSF 1e-8f
#define BMAX 32
#define BNMAX (32 * 4096)

// -------- scratch --------
__device__ float g_cs1[BNMAX];
__device__ float g_cs2[BNMAX];
__device__ float g_alp[BNMAX];
__device__ float g_cs4[BNMAX];
__device__ float g_s1[BNMAX];
__device__ float g_s2[BNMAX];
__device__ float g_nrm[BNMAX];
__device__ float g_nn1[BNMAX];   // ||c1 row||^2
__device__ float g_nn2[BNMAX];   // ||c2 row||^2
// 0=fn_addr 1=arg_addr 2=param_addr 3=body_addr 4=a_tag 5=a_l 6=a_r 7=b_tag 8=b_l 9=b_r
__device__ float g_vec[10][BMAX][128];

// -------- helpers --------
__device__ __forceinline__ float wsum(float v) {
#pragma unroll
    for (int m = 16; m > 0; m >>= 1) v += __shfl_xor_sync(0xffffffffu, v, m);
    return v;
}
__device__ __forceinline__ float dot4(const float4& a, const float4& b) {
    return a.x * b.x + a.y * b.y + a.z * b.z + a.w * b.w;
}
__device__ __forceinline__ void acc4(float4& acc, float s, const float4& v) {
    acc.x += s * v.x; acc.y += s * v.y; acc.z += s * v.z; acc.w += s * v.w;
}
__device__ __forceinline__ float4 mix4(float wa, const float4& a, float wb, const float4& b) {
    return make_float4(wa * a.x + wb * b.x, wa * a.y + wb * b.y,
                       wa * a.z + wb * b.z, wa * a.w + wb * b.w);
}
__device__ __forceinline__ float fdivg(float num, float den) {
    return __fdividef(num, fmaxf(den, EPSF));
}

__global__ void k_zero() {
    int i = blockIdx.x * blockDim.x + threadIdx.x;
    if (i < 10 * BMAX * 128) (&g_vec[0][0][0])[i] = 0.f;
}

// ============ K0: cs1, ||addr||, ||c1||^2, ||c2||^2; fn += cs1*c1; arg += cs1*c2 ============
__global__ void __launch_bounds__(256, 4) k_stage0(
    const float* __restrict__ at, const float* __restrict__ addr,
    const float* __restrict__ c1, const float* __restrict__ c2, int N)
{
    const int b = blockIdx.y;
    const int lane = threadIdx.x & 31;
    const int w = threadIdx.x >> 5;
    float4 q = reinterpret_cast<const float4*>(at)[b * 32 + lane];
    float nq = sqrtf(wsum(dot4(q, q)));
    float4 af = make_float4(0, 0, 0, 0), aa = make_float4(0, 0, 0, 0);
    int row0 = blockIdx.x * 64;
    int rend = min(row0 + 64, N);
#pragma unroll 2
    for (int r = row0 + w; r < rend; r += 8) {
        size_t off = ((size_t)(b * N + r)) * 32 + lane;
        float4 a  = reinterpret_cast<const float4*>(addr)[off];
        float4 v1 = reinterpret_cast<const float4*>(c1)[off];
        float4 v2 = reinterpret_cast<const float4*>(c2)[off];
        float dq = wsum(dot4(a, q));
        float na = sqrtf(wsum(dot4(a, a)));
        float n1 = wsum(dot4(v1, v1));
        float n2 = wsum(dot4(v2, v2));
        float cs = fdivg(dq, na * nq);
        if (lane == 0) {
            int bn = b * N + r;
            g_cs1[bn] = cs; g_nrm[bn] = na; g_nn1[bn] = n1; g_nn2[bn] = n2;
        }
        acc4(af, cs, v1);
        acc4(aa, cs, v2);
    }
    __shared__ float sf[128], sa[128];
    if (threadIdx.x < 128) { sf[threadIdx.x] = 0.f; sa[threadIdx.x] = 0.f; }
    __syncthreads();
    int base = lane * 4;
    atomicAdd(&sf[base + 0], af.x); atomicAdd(&sf[base + 1], af.y);
    atomicAdd(&sf[base + 2], af.z); atomicAdd(&sf[base + 3], af.w);
    atomicAdd(&sa[base + 0], aa.x); atomicAdd(&sa[base + 1], aa.y);
    atomicAdd(&sa[base + 2], aa.z); atomicAdd(&sa[base + 3], aa.w);
    __syncthreads();
    if (threadIdx.x < 128) {
        atomicAdd(&g_vec[0][b][threadIdx.x], sf[threadIdx.x]);
        atomicAdd(&g_vec[1][b][threadIdx.x], sa[threadIdx.x]);
    }
}

// ============ K1: cs2=cos(fn,·), cs3=cos(arg,·); 5 weighted sums ============
__global__ void __launch_bounds__(256, 4) k_stage1(
    const float* __restrict__ addr, const float* __restrict__ tg,
    const float* __restrict__ c1, const float* __restrict__ c2, int N)
{
    const int b = blockIdx.y;
    const int lane = threadIdx.x & 31;
    const int w = threadIdx.x >> 5;
    float4 qf = reinterpret_cast<const float4*>(&g_vec[0][b][0])[lane];
    float4 qa = reinterpret_cast<const float4*>(&g_vec[1][b][0])[lane];
    float nf  = sqrtf(wsum(dot4(qf, qf)));
    float nag = sqrtf(wsum(dot4(qa, qa)));
    float4 aP = make_float4(0,0,0,0), aB = make_float4(0,0,0,0);
    float4 aT = make_float4(0,0,0,0), aL = make_float4(0,0,0,0), aR = make_float4(0,0,0,0);
    int row0 = blockIdx.x * 64;
    int rend = min(row0 + 64, N);
#pragma unroll 2
    for (int r = row0 + w; r < rend; r += 8) {
        size_t off = ((size_t)(b * N + r)) * 32 + lane;
        float4 a  = reinterpret_cast<const float4*>(addr)[off];
        float4 vt = reinterpret_cast<const float4*>(tg)[off];
        float4 v1 = reinterpret_cast<const float4*>(c1)[off];
        float4 v2 = reinterpret_cast<const float4*>(c2)[off];
        float nr = g_nrm[b * N + r];
        float df = wsum(dot4(a, qf));
        float da = wsum(dot4(a, qa));
        float cs2 = fdivg(df, nr * nf);
        float cs3 = fdivg(da, nr * nag);
        if (lane == 0) g_cs2[b * N + r] = cs2;
        acc4(aT, cs3, vt);
        acc4(aP, cs2, v1); acc4(aL, cs3, v1);
        acc4(aB, cs2, v2); acc4(aR, cs3, v2);
    }
    __shared__ float s[5][128];
    for (int j = threadIdx.x; j < 5 * 128; j += 256) (&s[0][0])[j] = 0.f;
    __syncthreads();
    int base = lane * 4;
    atomicAdd(&s[0][base+0], aP.x); atomicAdd(&s[0][base+1], aP.y); atomicAdd(&s[0][base+2], aP.z); atomicAdd(&s[0][base+3], aP.w);
    atomicAdd(&s[1][base+0], aB.x); atomicAdd(&s[1][base+1], aB.y); atomicAdd(&s[1][base+2], aB.z); atomicAdd(&s[1][base+3], aB.w);
    atomicAdd(&s[2][base+0], aT.x); atomicAdd(&s[2][base+1], aT.y); atomicAdd(&s[2][base+2], aT.z); atomicAdd(&s[2][base+3], aT.w);
    atomicAdd(&s[3][base+0], aL.x); atomicAdd(&s[3][base+1], aL.y); atomicAdd(&s[3][base+2], aL.z); atomicAdd(&s[3][base+3], aL.w);
    atomicAdd(&s[4][base+0], aR.x); atomicAdd(&s[4][base+1], aR.y); atomicAdd(&s[4][base+2], aR.z); atomicAdd(&s[4][base+3], aR.w);
    __syncthreads();
    if (threadIdx.x < 128) {
        atomicAdd(&g_vec[2][b][threadIdx.x], s[0][threadIdx.x]);
        atomicAdd(&g_vec[3][b][threadIdx.x], s[1][threadIdx.x]);
        atomicAdd(&g_vec[4][b][threadIdx.x], s[2][threadIdx.x]);
        atomicAdd(&g_vec[5][b][threadIdx.x], s[3][threadIdx.x]);
        atomicAdd(&g_vec[6][b][threadIdx.x], s[4][threadIdx.x]);
    }
}

// ============ K2: row-pair (2 rows/warp, 16 lanes each), 6 reductions, 4-level butterflies ============
__global__ void __launch_bounds__(256, 4) k_stage2(
    const float* __restrict__ addr, const float* __restrict__ tg,
    const float* __restrict__ c1, const float* __restrict__ c2, int N)
{
    const int b = blockIdx.y;
    const int tid = threadIdx.x;
    const int lane = tid & 31;
    const int wid = tid >> 5;
    const int sl = lane & 15;
    const int half = lane >> 4;

    __shared__ float4 sq[4][64];  // 0=qp 1=qb 2=qal 3=qar, each replicated 2x (anti-hoist)
    float4 qp  = reinterpret_cast<const float4*>(&g_vec[2][b][0])[lane];
    float4 qb  = reinterpret_cast<const float4*>(&g_vec[3][b][0])[lane];
    float4 qal = reinterpret_cast<const float4*>(&g_vec[5][b][0])[lane];
    float4 qar = reinterpret_cast<const float4*>(&g_vec[6][b][0])[lane];
    if (wid == 0) {
        sq[0][lane] = qp;  sq[0][32 + lane] = qp;
        sq[1][lane] = qb;  sq[1][32 + lane] = qb;
        sq[2][lane] = qal; sq[2][32 + lane] = qal;
        sq[3][lane] = qar; sq[3][32 + lane] = qar;
    }
    float np    = sqrtf(wsum(dot4(qp, qp)));
    float nb    = sqrtf(wsum(dot4(qb, qb)));
    float kalp  = wsum(dot4(qal, qp));
    float karp  = wsum(dot4(qar, qp));
    float kalal = wsum(dot4(qal, qal));
    float karar = wsum(dot4(qar, qar));
    __syncthreads();

    const float4* addr4 = reinterpret_cast<const float4*>(addr);
    const float4* tg4 = reinterpret_cast<const float4*>(tg);
    const float4* c14 = reinterpret_cast<const float4*>(c1);
    const float4* c24 = reinterpret_cast<const float4*>(c2);

    float4 At0 = make_float4(0,0,0,0), At1 = make_float4(0,0,0,0);
    float4 A10 = make_float4(0,0,0,0), A11 = make_float4(0,0,0,0);
    float4 A20 = make_float4(0,0,0,0), A21 = make_float4(0,0,0,0);
    float St = 0.f, S1al = 0.f, S1g = 0.f, S2ar = 0.f, S2g = 0.f;

    int row0 = blockIdx.x * 64;
#pragma unroll 1
    for (int it = 0; it < 4; ++it) {
        int row = row0 + it * 16 + wid * 2 + half;
        bool valid = (row < N);
        int rowc = valid ? row : (N - 1);
        size_t rb = ((size_t)(b * N + rowc)) * 32;
        int cb = (it & 1) << 5;         // loop-variant smem copy base (anti-hoist)
        float dp, db, d1p, x1, d2p, x2;
        {
            float4 qp0 = sq[0][cb + sl], qp1 = sq[0][cb + sl + 16];
            {
                float4 a0 = addr4[rb + sl];
                float4 a1 = addr4[rb + sl + 16];
                float4 q0 = sq[1][cb + sl], q1 = sq[1][cb + sl + 16];
                dp = dot4(a0, qp0) + dot4(a1, qp1);
                db = dot4(a0, q0)  + dot4(a1, q1);
            }
            {
                float4 v0 = c14[rb + sl];
                float4 v1 = c14[rb + sl + 16];
                float4 q0 = sq[2][cb + sl], q1 = sq[2][cb + sl + 16];
                d1p = dot4(v0, qp0) + dot4(v1, qp1);
                x1  = dot4(v0, q0)  + dot4(v1, q1);
            }
            {
                float4 v0 = c24[rb + sl];
                float4 v1 = c24[rb + sl + 16];
                float4 q0 = sq[3][cb + sl], q1 = sq[3][cb + sl + 16];
                d2p = dot4(v0, qp0) + dot4(v1, qp1);
                x2  = dot4(v0, q0)  + dot4(v1, q1);
            }
        }
#pragma unroll
        for (int m = 8; m > 0; m >>= 1) {
            dp  += __shfl_xor_sync(0xffffffffu, dp, m);
            db  += __shfl_xor_sync(0xffffffffu, db, m);
            d1p += __shfl_xor_sync(0xffffffffu, d1p, m);
            x1  += __shfl_xor_sync(0xffffffffu, x1, m);
            d2p += __shfl_xor_sync(0xffffffffu, d2p, m);
            x2  += __shfl_xor_sync(0xffffffffu, x2, m);
        }
        int bn = b * N + rowc;
        float nr = g_nrm[bn];
        float n1 = g_nn1[bn];
        float n2 = g_nn2[bn];
        float alr = fdivg(dp, nr * np);
        float alpha = (alr > EPSF) ? alr : 0.f;
        float ia = 1.f - alpha;
        float cs4 = fdivg(db, nr * nb);
        float du1 = ia * d1p + alpha * kalp;
        float nu1 = sqrtf(fmaxf(ia*ia*n1 + 2.f*ia*alpha*x1 + alpha*alpha*kalal, 0.f));
        float s1 = fdivg(du1, nu1 * np);
        float du2 = ia * d2p + alpha * karp;
        float nu2 = sqrtf(fmaxf(ia*ia*n2 + 2.f*ia*alpha*x2 + alpha*alpha*karar, 0.f));
        float s2 = fdivg(du2, nu2 * np);
        if (valid && sl == 0) {
            g_alp[bn] = alpha; g_s1[bn] = s1; g_s2[bn] = s2; g_cs4[bn] = cs4;
        }
        if (!valid) cs4 = 0.f;
        float wt = cs4 * ia;
        float w1 = cs4 * (1.f - s1) * ia;
        float w2 = cs4 * (1.f - s2) * ia;
        if (sl == 0) {
            St   += cs4 * alpha;
            S1al += cs4 * (1.f - s1) * alpha;
            S1g  += cs4 * s1;
            S2ar += cs4 * (1.f - s2) * alpha;
            S2g  += cs4 * s2;
        }
        // accumulate: vt fresh, v1/v2 L1-hot reloads
        float4 t0 = tg4[rb + sl], t1 = tg4[rb + sl + 16];
        acc4(At0, wt, t0); acc4(At1, wt, t1);
        t0 = c14[rb + sl]; t1 = c14[rb + sl + 16];
        acc4(A10, w1, t0); acc4(A11, w1, t1);
        t0 = c24[rb + sl]; t1 = c24[rb + sl + 16];
        acc4(A20, w2, t0); acc4(A21, w2, t1);
    }
    // warp totals of scalar coefficients
    St = wsum(St); S1al = wsum(S1al); S1g = wsum(S1g); S2ar = wsum(S2ar); S2g = wsum(S2g);
    // fold q-vector terms once per warp (half 0 only, both position sets)
    if (half == 0) {
        float4 qtag0 = reinterpret_cast<const float4*>(&g_vec[4][b][0])[sl];
        float4 qtag1 = reinterpret_cast<const float4*>(&g_vec[4][b][0])[sl + 16];
        float4 qarg0 = reinterpret_cast<const float4*>(&g_vec[1][b][0])[sl];
        float4 qarg1 = reinterpret_cast<const float4*>(&g_vec[1][b][0])[sl + 16];
        float4 qal0 = sq[2][sl], qal1 = sq[2][sl + 16];
        float4 qar0 = sq[3][sl], qar1 = sq[3][sl + 16];
        acc4(At0, St, qtag0);  acc4(At1, St, qtag1);
        acc4(A10, S1al, qal0); acc4(A11, S1al, qal1);
        acc4(A10, S1g, qarg0); acc4(A11, S1g, qarg1);
        acc4(A20, S2ar, qar0); acc4(A21, S2ar, qar1);
        acc4(A20, S2g, qarg0); acc4(A21, S2g, qarg1);
    }
    __shared__ float s[3][128];
    for (int j = tid; j < 3 * 128; j += 256) (&s[0][0])[j] = 0.f;
    __syncthreads();
    int b0 = sl * 4, b1 = (sl + 16) * 4;
    atomicAdd(&s[0][b0+0], At0.x); atomicAdd(&s[0][b0+1], At0.y); atomicAdd(&s[0][b0+2], At0.z); atomicAdd(&s[0][b0+3], At0.w);
    atomicAdd(&s[0][b1+0], At1.x); atomicAdd(&s[0][b1+1], At1.y); atomicAdd(&s[0][b1+2], At1.z); atomicAdd(&s[0][b1+3], At1.w);
    atomicAdd(&s[1][b0+0], A10.x); atomicAdd(&s[1][b0+1], A10.y); atomicAdd(&s[1][b0+2], A10.z); atomicAdd(&s[1][b0+3], A10.w);
    atomicAdd(&s[1][b1+0], A11.x); atomicAdd(&s[1][b1+1], A11.y); atomicAdd(&s[1][b1+2], A11.z); atomicAdd(&s[1][b1+3], A11.w);
    atomicAdd(&s[2][b0+0], A20.x); atomicAdd(&s[2][b0+1], A20.y); atomicAdd(&s[2][b0+2], A20.z); atomicAdd(&s[2][b0+3], A20.w);
    atomicAdd(&s[2][b1+0], A21.x); atomicAdd(&s[2][b1+1], A21.y); atomicAdd(&s[2][b1+2], A21.z); atomicAdd(&s[2][b1+3], A21.w);
    __syncthreads();
    if (tid < 128) {
        atomicAdd(&g_vec[7][b][tid], s[0][tid]);
        atomicAdd(&g_vec[8][b][tid], s[1][tid]);
        atomicAdd(&g_vec[9][b][tid], s[2][tid]);
    }
}

// ============ K3: reconstruct rows + insert(at, b_*) + closed-form GC ============
__global__ void __launch_bounds__(256) k_stage3(
    const float* __restrict__ tg, const float* __restrict__ c1, const float* __restrict__ c2,
    const float* __restrict__ zv, const int* __restrict__ gsp,
    float* __restrict__ ot, float* __restrict__ o1, float* __restrict__ o2,
    int B, int N)
{
    int i = blockIdx.x * blockDim.x + threadIdx.x;
    int total = B * N * 32;
    if (i >= total) return;
    int d4 = i & 31;
    int bn = i >> 5;
    int b = bn / N;
    float a1 = g_cs1[bn]; a1 = (a1 > EPSF) ? a1 : 0.f;
    float cf = g_cs2[bn]; cf = (cf > EPSF) ? cf : 0.f;
    float cp = g_alp[bn];
    float cb = g_cs4[bn]; cb = (cb > EPSF) ? cb : 0.f;
    float s1 = g_s1[bn], s2 = g_s2[bn];
    float base = (1.f - cf) * (1.f - cp) * (1.f - cb);
    int g = *gsp;
    float P = 1.f;
    for (int k = 0; k < g; k++) P *= base;
    float ia1 = 1.f - a1, icp = 1.f - cp, iP = 1.f - P;
    float4 z    = reinterpret_cast<const float4*>(zv)[d4];
    float4 qarg = reinterpret_cast<const float4*>(&g_vec[1][b][0])[d4];
    float4 qtag = reinterpret_cast<const float4*>(&g_vec[4][b][0])[d4];
    float4 qal  = reinterpret_cast<const float4*>(&g_vec[5][b][0])[d4];
    float4 qar  = reinterpret_cast<const float4*>(&g_vec[6][b][0])[d4];
    float4 bt   = reinterpret_cast<const float4*>(&g_vec[7][b][0])[d4];
    float4 bl   = reinterpret_cast<const float4*>(&g_vec[8][b][0])[d4];
    float4 br   = reinterpret_cast<const float4*>(&g_vec[9][b][0])[d4];

    float4 t = reinterpret_cast<const float4*>(tg)[i];
    t = mix4(icp, t, cp, qtag);
    t = mix4(ia1, t, a1, bt);
    reinterpret_cast<float4*>(ot)[i] = mix4(P, t, iP, z);

    t = reinterpret_cast<const float4*>(c1)[i];
    t = mix4(icp, t, cp, qal);
    t = mix4(1.f - s1, t, s1, qarg);
    t = mix4(ia1, t, a1, bl);
    reinterpret_cast<float4*>(o1)[i] = mix4(P, t, iP, z);

    t = reinterpret_cast<const float4*>(c2)[i];
    t = mix4(icp, t, cp, qar);
    t = mix4(1.f - s2, t, s2, qarg);
    t = mix4(ia1, t, a1, br);
    reinterpret_cast<float4*>(o2)[i] = mix4(P, t, iP, z);
}

// ============ launch ============
extern "C" void kernel_launch(void* const* d_in, const int* in_sizes, int n_in,
                              void* d_out, int out_size)
{
    const float* at   = (const float*)d_in[0];
    const float* addr = (const float*)d_in[1];
    const float* tg   = (const float*)d_in[2];
    const float* c1   = (const float*)d_in[3];
    const float* c2   = (const float*)d_in[4];
    const float* zv   = (const float*)d_in[5];
    const int*   gs   = (const int*)d_in[6];

    int D = in_sizes[5];
    int B = in_sizes[0] / D;
    int N = in_sizes[1] / in_sizes[0];

    size_t stride = (size_t)B * N * D;
    float* ot = (float*)d_out;
    float* o1 = ot + stride;
    float* o2 = o1 + stride;

    k_zero<<<(10 * BMAX * 128 + 255) / 256, 256>>>();

    dim3 grid((N + 63) / 64, B);
    k_stage0<<<grid, 256>>>(at, addr, c1, c2, N);
    k_stage1<<<grid, 256>>>(addr, tg, c1, c2, N);
    k_stage2<<<grid, 256>>>(addr, tg, c1, c2, N);

    int tot4 = B * N * (D / 4);
    k_stage3<<<(tot4 + 255) / 256, 256>>>(tg, c1, c2, zv, gs, ot, o1, o2, B, N);

    (void)n_in; (void)out_size;
}